// round 1
// baseline (speedup 1.0000x reference)
#include <cuda_runtime.h>

// ---------------------------------------------------------------------------
// LapImage: 4-scale trilinear grid_sample (align_corners=True, zeros pad), sum.
//   coords: [4,96,96,96,3] float32  (gx->W, gy->H, gz->D)
//   img0:   [3,32,32,32]   img1: [3,32,64,64]
//   img2:   [3,32,128,128] img3: [3,32,256,256]
//   out:    [4,3,96,96,96] float32
//
// Strategy: repack each volume from [C,D,H,W] to channel-interleaved
// float4[D*H*W] so each trilinear corner is a single aligned 16B gather
// (3x fewer l1tex wavefronts than 24 scalar gathers). Volumes are fully
// L2-resident (~32MB << 126MB), so the kernel is l1tex/L2-gather bound.
// ---------------------------------------------------------------------------

static constexpr int D0 = 32, H0 = 32,  W0 = 32;
static constexpr int D1 = 32, H1 = 64,  W1 = 64;
static constexpr int D2 = 32, H2 = 128, W2 = 128;
static constexpr int D3 = 32, H3 = 256, W3 = 256;
static constexpr int NV0 = D0 * H0 * W0;   //   32768
static constexpr int NV1 = D1 * H1 * W1;   //  131072
static constexpr int NV2 = D2 * H2 * W2;   //  524288
static constexpr int NV3 = D3 * H3 * W3;   // 2097152
static constexpr int NV_TOTAL = NV0 + NV1 + NV2 + NV3;

static constexpr int BVOL = 96 * 96 * 96;  // per-batch output voxels (884736)
static constexpr int NPTS = 4 * BVOL;      // 3538944 sample points

// Channel-interleaved scratch (static __device__ arrays: allocation-guard legal)
__device__ float4 g_p0[NV0];
__device__ float4 g_p1[NV1];
__device__ float4 g_p2[NV2];
__device__ float4 g_p3[NV3];

// ---------------------------------------------------------------------------
// Pack kernel: [3, D,H,W] -> float4[D*H*W] = (c0, c1, c2, 0)
// One launch covers all four volumes (contiguous index ranges).
// ---------------------------------------------------------------------------
__global__ void __launch_bounds__(256) pack_kernel(
    const float* __restrict__ s0, const float* __restrict__ s1,
    const float* __restrict__ s2, const float* __restrict__ s3)
{
    int i = blockIdx.x * 256 + threadIdx.x;
    if (i < NV0) {
        g_p0[i] = make_float4(s0[i], s0[i + NV0], s0[i + 2 * NV0], 0.0f);
        return;
    }
    i -= NV0;
    if (i < NV1) {
        g_p1[i] = make_float4(s1[i], s1[i + NV1], s1[i + 2 * NV1], 0.0f);
        return;
    }
    i -= NV1;
    if (i < NV2) {
        g_p2[i] = make_float4(s2[i], s2[i + NV2], s2[i + 2 * NV2], 0.0f);
        return;
    }
    i -= NV2;
    if (i < NV3) {
        g_p3[i] = make_float4(s3[i], s3[i + NV3], s3[i + 2 * NV3], 0.0f);
    }
}

// ---------------------------------------------------------------------------
// Per-volume trilinear sample-and-accumulate.
// align_corners=True:  ix = (gx+1)*0.5*(W-1)
// coords guaranteed in [-1,1) -> indices in range; clamps kept for safety
// (weights are exactly 0 whenever a clamp would engage, matching zeros-pad).
// ---------------------------------------------------------------------------
template <int D, int H, int W>
__device__ __forceinline__ void sample_vol(
    const float4* __restrict__ vol,
    float gx, float gy, float gz,
    float& ax, float& ay, float& az)
{
    const float hx = 0.5f * (float)(W - 1);
    const float hy = 0.5f * (float)(H - 1);
    const float hz = 0.5f * (float)(D - 1);
    float ix = fmaf(gx, hx, hx);
    float iy = fmaf(gy, hy, hy);
    float iz = fmaf(gz, hz, hz);

    float xf = floorf(ix), yf = floorf(iy), zf = floorf(iz);
    float fx = ix - xf,    fy = iy - yf,    fz = iz - zf;

    int x0 = (int)xf, y0 = (int)yf, z0 = (int)zf;
    x0 = max(0, min(x0, W - 1));
    y0 = max(0, min(y0, H - 1));
    z0 = max(0, min(z0, D - 1));
    int x1 = min(x0 + 1, W - 1);
    int y1 = min(y0 + 1, H - 1);
    int z1 = min(z0 + 1, D - 1);

    int r00 = (z0 * H + y0) * W;   // (z0, y0)
    int r01 = (z0 * H + y1) * W;   // (z0, y1)
    int r10 = (z1 * H + y0) * W;   // (z1, y0)
    int r11 = (z1 * H + y1) * W;   // (z1, y1)

    // 8 independent 16B gathers — issue all before consuming (MLP).
    float4 v000 = __ldg(vol + r00 + x0);
    float4 v001 = __ldg(vol + r00 + x1);
    float4 v010 = __ldg(vol + r01 + x0);
    float4 v011 = __ldg(vol + r01 + x1);
    float4 v100 = __ldg(vol + r10 + x0);
    float4 v101 = __ldg(vol + r10 + x1);
    float4 v110 = __ldg(vol + r11 + x0);
    float4 v111 = __ldg(vol + r11 + x1);

    float ex = 1.0f - fx, ey = 1.0f - fy, ez = 1.0f - fz;
    float w000 = ez * ey * ex;
    float w001 = ez * ey * fx;
    float w010 = ez * fy * ex;
    float w011 = ez * fy * fx;
    float w100 = fz * ey * ex;
    float w101 = fz * ey * fx;
    float w110 = fz * fy * ex;
    float w111 = fz * fy * fx;

    ax = fmaf(w000, v000.x, ax); ay = fmaf(w000, v000.y, ay); az = fmaf(w000, v000.z, az);
    ax = fmaf(w001, v001.x, ax); ay = fmaf(w001, v001.y, ay); az = fmaf(w001, v001.z, az);
    ax = fmaf(w010, v010.x, ax); ay = fmaf(w010, v010.y, ay); az = fmaf(w010, v010.z, az);
    ax = fmaf(w011, v011.x, ax); ay = fmaf(w011, v011.y, ay); az = fmaf(w011, v011.z, az);
    ax = fmaf(w100, v100.x, ax); ay = fmaf(w100, v100.y, ay); az = fmaf(w100, v100.z, az);
    ax = fmaf(w101, v101.x, ax); ay = fmaf(w101, v101.y, ay); az = fmaf(w101, v101.z, az);
    ax = fmaf(w110, v110.x, ax); ay = fmaf(w110, v110.y, ay); az = fmaf(w110, v110.z, az);
    ax = fmaf(w111, v111.x, ax); ay = fmaf(w111, v111.y, ay); az = fmaf(w111, v111.z, az);
}

// ---------------------------------------------------------------------------
// Main kernel: one thread per sample point; sums all 4 volumes; writes
// 3 output floats (coalesced, stride BVOL between channels).
// ---------------------------------------------------------------------------
__global__ void __launch_bounds__(256) lapimage_sample_kernel(
    const float* __restrict__ coords, float* __restrict__ out)
{
    int n = blockIdx.x * 256 + threadIdx.x;
    if (n >= NPTS) return;

    float gx = __ldg(coords + 3 * n + 0);
    float gy = __ldg(coords + 3 * n + 1);
    float gz = __ldg(coords + 3 * n + 2);

    float ax = 0.0f, ay = 0.0f, az = 0.0f;
    sample_vol<D0, H0, W0>(g_p0, gx, gy, gz, ax, ay, az);
    sample_vol<D1, H1, W1>(g_p1, gx, gy, gz, ax, ay, az);
    sample_vol<D2, H2, W2>(g_p2, gx, gy, gz, ax, ay, az);
    sample_vol<D3, H3, W3>(g_p3, gx, gy, gz, ax, ay, az);

    int b = n / BVOL;
    int v = n - b * BVOL;
    float* o = out + (size_t)(b * 3) * BVOL + v;
    o[0]         = ax;
    o[BVOL]      = ay;
    o[2 * BVOL]  = az;
}

// ---------------------------------------------------------------------------
// Launch
// ---------------------------------------------------------------------------
extern "C" void kernel_launch(void* const* d_in, const int* in_sizes, int n_in,
                              void* d_out, int out_size)
{
    const float* coords = (const float*)d_in[0];
    const float* img0   = (const float*)d_in[1];
    const float* img1   = (const float*)d_in[2];
    const float* img2   = (const float*)d_in[3];
    const float* img3   = (const float*)d_in[4];
    float*       out    = (float*)d_out;

    // 1) Repack volumes to channel-interleaved float4 (one launch).
    {
        int blocks = (NV_TOTAL + 255) / 256;
        pack_kernel<<<blocks, 256>>>(img0, img1, img2, img3);
    }

    // 2) Sample + sum.
    {
        int blocks = (NPTS + 255) / 256;
        lapimage_sample_kernel<<<blocks, 256>>>(coords, out);
    }
}

// round 2
// speedup vs baseline: 1.5795x; 1.5795x over previous
#include <cuda_runtime.h>
#include <cuda_fp16.h>

// ---------------------------------------------------------------------------
// LapImage R2: fp16 channel-packed voxels + x-pair fusion.
//
// Each voxel -> half4 (c0,c1,c2,pad) = 8B. The two x-corners (x0,x0+1) are
// 16 contiguous bytes -> ONE LDG.128 per corner-row (4 gathers/volume instead
// of 8 -> l1tex wavefronts halved; l1tex was the 94.8% binding pipe in R1).
// 16B alignment for odd x0 via a one-voxel-shifted duplicate copy (E/O).
// Coords staged through shared memory to make their loads float4-coalesced.
// ---------------------------------------------------------------------------

static constexpr int D0 = 32, H0 = 32,  W0 = 32;
static constexpr int D1 = 32, H1 = 64,  W1 = 64;
static constexpr int D2 = 32, H2 = 128, W2 = 128;
static constexpr int D3 = 32, H3 = 256, W3 = 256;
static constexpr int NV0 = D0 * H0 * W0;   //   32768
static constexpr int NV1 = D1 * H1 * W1;   //  131072
static constexpr int NV2 = D2 * H2 * W2;   //  524288
static constexpr int NV3 = D3 * H3 * W3;   // 2097152
static constexpr int NV_TOTAL = NV0 + NV1 + NV2 + NV3;   // 2785280

static constexpr int BVOL = 96 * 96 * 96;  // 884736
static constexpr int NPTS = 4 * BVOL;      // 3538944 (= 13824 * 256 exactly)

// E[i] = half4(vox i); O[i] = half4(vox i+1). Both 16B-aligned so that the
// pair (x0, x0+1) is always one aligned 16B load (select E/O by x0 parity).
__device__ __align__(16) uint2 g_e0[NV0];  __device__ __align__(16) uint2 g_o0[NV0];
__device__ __align__(16) uint2 g_e1[NV1];  __device__ __align__(16) uint2 g_o1[NV1];
__device__ __align__(16) uint2 g_e2[NV2];  __device__ __align__(16) uint2 g_o2[NV2];
__device__ __align__(16) uint2 g_e3[NV3];  __device__ __align__(16) uint2 g_o3[NV3];

// ---------------------------------------------------------------------------
// Pack: [3,D,H,W] fp32 -> half4 voxels, written to E[i] and O[i-1].
// ---------------------------------------------------------------------------
__device__ __forceinline__ void pack_one(const float* __restrict__ s, int i, int nv,
                                         uint2* __restrict__ E, uint2* __restrict__ O)
{
    __half h0 = __float2half_rn(s[i]);
    __half h1 = __float2half_rn(s[i + nv]);
    __half h2 = __float2half_rn(s[i + 2 * nv]);
    __half2 lo = __halves2half2(h0, h1);
    __half2 hi = __halves2half2(h2, __ushort_as_half((unsigned short)0));
    uint2 u;
    u.x = *reinterpret_cast<unsigned int*>(&lo);
    u.y = *reinterpret_cast<unsigned int*>(&hi);
    E[i] = u;
    if (i > 0) O[i - 1] = u;
}

__global__ void __launch_bounds__(256) pack_kernel(
    const float* __restrict__ s0, const float* __restrict__ s1,
    const float* __restrict__ s2, const float* __restrict__ s3)
{
    int i = blockIdx.x * 256 + threadIdx.x;
    if (i < NV0) { pack_one(s0, i, NV0, g_e0, g_o0); return; }
    i -= NV0;
    if (i < NV1) { pack_one(s1, i, NV1, g_e1, g_o1); return; }
    i -= NV1;
    if (i < NV2) { pack_one(s2, i, NV2, g_e2, g_o2); return; }
    i -= NV2;
    if (i < NV3) { pack_one(s3, i, NV3, g_e3, g_o3); }
}

// ---------------------------------------------------------------------------
// Consume one 16B pair-load: halves [a0,a1,a2,_, b0,b1,b2,_]
// acc += w * lerp(a, b, fx)   (per channel, fp32 math)
// ---------------------------------------------------------------------------
__device__ __forceinline__ void acc_pair(uint4 q, float w, float fx,
                                         float& ax, float& ay, float& az)
{
    const __half2* h = reinterpret_cast<const __half2*>(&q);
    float2 a01 = __half22float2(h[0]);
    float  a2  = __low2float(h[1]);
    float2 b01 = __half22float2(h[2]);
    float  b2  = __low2float(h[3]);
    float cx = fmaf(fx, b01.x - a01.x, a01.x);
    float cy = fmaf(fx, b01.y - a01.y, a01.y);
    float cz = fmaf(fx, b2    - a2,    a2);
    ax = fmaf(w, cx, ax);
    ay = fmaf(w, cy, ay);
    az = fmaf(w, cz, az);
}

// ---------------------------------------------------------------------------
// Per-volume trilinear sample: 4 pair-gathers (one per (z,y) corner row).
// align_corners=True; coords in [-1,1) so x0<=W-2 after clamp and weights
// already encode any boundary case exactly.
// ---------------------------------------------------------------------------
template <int D, int H, int W>
__device__ __forceinline__ void sample_vol(
    const uint2* __restrict__ E, const uint2* __restrict__ O,
    float gx, float gy, float gz,
    float& ax, float& ay, float& az)
{
    const float hx = 0.5f * (float)(W - 1);
    const float hy = 0.5f * (float)(H - 1);
    const float hz = 0.5f * (float)(D - 1);
    float ix = fminf(fmaxf(fmaf(gx, hx, hx), 0.0f), (float)(W - 1));
    float iy = fminf(fmaxf(fmaf(gy, hy, hy), 0.0f), (float)(H - 1));
    float iz = fminf(fmaxf(fmaf(gz, hz, hz), 0.0f), (float)(D - 1));

    int x0 = min((int)ix, W - 2);          // pair (x0, x0+1) always valid
    int y0 = min((int)iy, H - 2);
    int z0 = min((int)iz, D - 2);
    float fx = ix - (float)x0;
    float fy = iy - (float)y0;
    float fz = iz - (float)z0;

    int r00 = (z0 * H + y0) * W;           // rows are even-based (W even)
    int r01 = r00 + W;                     // (z0, y0+1)
    int r10 = r00 + H * W;                 // (z0+1, y0)
    int r11 = r10 + W;

    int odd = x0 & 1;
    const uint2* arr = odd ? O : E;
    int xo = x0 - odd;                     // 16B-aligned uint2 offset

    const uint4* p00 = reinterpret_cast<const uint4*>(arr + (r00 + xo));
    const uint4* p01 = reinterpret_cast<const uint4*>(arr + (r01 + xo));
    const uint4* p10 = reinterpret_cast<const uint4*>(arr + (r10 + xo));
    const uint4* p11 = reinterpret_cast<const uint4*>(arr + (r11 + xo));
    uint4 q00 = __ldg(p00);
    uint4 q01 = __ldg(p01);
    uint4 q10 = __ldg(p10);
    uint4 q11 = __ldg(p11);

    float ez = 1.0f - fz, ey = 1.0f - fy;
    acc_pair(q00, ez * ey, fx, ax, ay, az);
    acc_pair(q01, ez * fy, fx, ax, ay, az);
    acc_pair(q10, fz * ey, fx, ax, ay, az);
    acc_pair(q11, fz * fy, fx, ax, ay, az);
}

// ---------------------------------------------------------------------------
// Main kernel: coords staged via smem (float4-coalesced), one point/thread.
// ---------------------------------------------------------------------------
__global__ void __launch_bounds__(256) lapimage_sample_kernel(
    const float* __restrict__ coords, float* __restrict__ out)
{
    __shared__ float sc[768];              // 256 points * 3 floats

    int t = threadIdx.x;
    int blk_base = blockIdx.x * 256;       // first point of this block

    // Coalesced stage-in: 768 floats = 192 float4 loads.
    const float4* c4 = reinterpret_cast<const float4*>(coords + (size_t)blk_base * 3);
    if (t < 192) {
        float4 v = __ldg(c4 + t);
        sc[4 * t + 0] = v.x;
        sc[4 * t + 1] = v.y;
        sc[4 * t + 2] = v.z;
        sc[4 * t + 3] = v.w;
    }
    __syncthreads();

    float gx = sc[3 * t + 0];
    float gy = sc[3 * t + 1];
    float gz = sc[3 * t + 2];

    float ax = 0.0f, ay = 0.0f, az = 0.0f;
    sample_vol<D0, H0, W0>(g_e0, g_o0, gx, gy, gz, ax, ay, az);
    sample_vol<D1, H1, W1>(g_e1, g_o1, gx, gy, gz, ax, ay, az);
    sample_vol<D2, H2, W2>(g_e2, g_o2, gx, gy, gz, ax, ay, az);
    sample_vol<D3, H3, W3>(g_e3, g_o3, gx, gy, gz, ax, ay, az);

    int n = blk_base + t;
    int b = n / BVOL;
    int v = n - b * BVOL;
    float* o = out + (size_t)(b * 3) * BVOL + v;
    o[0]        = ax;
    o[BVOL]     = ay;
    o[2 * BVOL] = az;
}

// ---------------------------------------------------------------------------
// Launch
// ---------------------------------------------------------------------------
extern "C" void kernel_launch(void* const* d_in, const int* in_sizes, int n_in,
                              void* d_out, int out_size)
{
    const float* coords = (const float*)d_in[0];
    const float* img0   = (const float*)d_in[1];
    const float* img1   = (const float*)d_in[2];
    const float* img2   = (const float*)d_in[3];
    const float* img3   = (const float*)d_in[4];
    float*       out    = (float*)d_out;

    pack_kernel<<<NV_TOTAL / 256, 256>>>(img0, img1, img2, img3);
    lapimage_sample_kernel<<<NPTS / 256, 256>>>(coords, out);
}